// round 7
// baseline (speedup 1.0000x reference)
#include <cuda_runtime.h>
#include <cuda_bf16.h>
#include <math.h>
#include <stdint.h>

#define N_TOK 8192
#define D_IN  1024
#define D_HEAD 128

typedef uint32_t u32;

// ---------------------------------------------------------------------------
// Device-global scratch.
// ---------------------------------------------------------------------------
__device__ __align__(16) __nv_bfloat16 g_Xh[(size_t)N_TOK * D_IN];
__device__ __align__(16) __nv_bfloat16 g_Xl[(size_t)N_TOK * D_IN];
__device__ __align__(16) __nv_bfloat16 g_Wh[3 * D_HEAD * D_IN];
__device__ __align__(16) __nv_bfloat16 g_Wl[3 * D_HEAD * D_IN];
__device__ __align__(16) __nv_bfloat16 g_Qh[N_TOK * D_HEAD];
__device__ __align__(16) __nv_bfloat16 g_Ql[N_TOK * D_HEAD];
__device__ __align__(16) __nv_bfloat16 g_Kh[N_TOK * D_HEAD];
__device__ __align__(16) __nv_bfloat16 g_Kl[N_TOK * D_HEAD];
__device__ __align__(16) __nv_bfloat16 g_Vth[N_TOK * D_HEAD];
__device__ __align__(16) __nv_bfloat16 g_Vtl[N_TOK * D_HEAD];

__device__ __forceinline__ void split_bf16(float v, __nv_bfloat16& h, __nv_bfloat16& l) {
  h = __float2bfloat16(v);
  l = __float2bfloat16(v - __bfloat162float(h));
}

__device__ __forceinline__ u32 smem_u32(const void* p) {
  u32 a;
  asm("{ .reg .u64 t; cvta.to.shared.u64 t, %1; cvt.u32.u64 %0, t; }" : "=r"(a) : "l"(p));
  return a;
}
__device__ __forceinline__ void cp16(u32 dst, const void* src) {
  asm volatile("cp.async.cg.shared.global [%0], [%1], 16;" :: "r"(dst), "l"(src));
}
#define CP_COMMIT() asm volatile("cp.async.commit_group;" ::: "memory")
#define CP_WAIT0()  asm volatile("cp.async.wait_group 0;" ::: "memory")
#define CP_WAIT1()  asm volatile("cp.async.wait_group 1;" ::: "memory")
#define CP_WAIT2()  asm volatile("cp.async.wait_group 2;" ::: "memory")

// m16n8k16 row.col bf16 -> f32 (HMMA; portable PTX)
__device__ __forceinline__ void mma16816(float* d, u32 a0, u32 a1, u32 a2, u32 a3,
                                         u32 b0, u32 b1) {
  asm volatile(
      "mma.sync.aligned.m16n8k16.row.col.f32.bf16.bf16.f32 "
      "{%0,%1,%2,%3}, {%4,%5,%6,%7}, {%8,%9}, {%0,%1,%2,%3};"
      : "+f"(d[0]), "+f"(d[1]), "+f"(d[2]), "+f"(d[3])
      : "r"(a0), "r"(a1), "r"(a2), "r"(a3), "r"(b0), "r"(b1));
}
__device__ __forceinline__ u32 cvt2(float hi, float lo) {
  u32 d;
  asm("cvt.rn.bf16x2.f32 %0, %1, %2;" : "=r"(d) : "f"(hi), "f"(lo));
  return d;
}

// ---------------------------------------------------------------------------
// Split kernels: fp32 -> bf16 hi/lo.
// ---------------------------------------------------------------------------
__device__ __forceinline__ void split8_store(const float* v, __nv_bfloat16* dh,
                                             __nv_bfloat16* dl) {
  u32 hw[4], lw[4];
#pragma unroll
  for (int j = 0; j < 4; j++) {
    __nv_bfloat16 h0, l0, h1, l1;
    split_bf16(v[2 * j], h0, l0);
    split_bf16(v[2 * j + 1], h1, l1);
    hw[j] = ((u32)__bfloat16_as_ushort(h1) << 16) | __bfloat16_as_ushort(h0);
    lw[j] = ((u32)__bfloat16_as_ushort(l1) << 16) | __bfloat16_as_ushort(l0);
  }
  *(uint4*)dh = make_uint4(hw[0], hw[1], hw[2], hw[3]);
  *(uint4*)dl = make_uint4(lw[0], lw[1], lw[2], lw[3]);
}

__global__ __launch_bounds__(256) void split_x_kernel(const float* __restrict__ X) {
  size_t i = ((size_t)blockIdx.x * 256 + threadIdx.x) * 8;
  float4 f0 = *(const float4*)&X[i];
  float4 f1 = *(const float4*)&X[i + 4];
  float v[8] = {f0.x, f0.y, f0.z, f0.w, f1.x, f1.y, f1.z, f1.w};
  split8_store(v, &g_Xh[i], &g_Xl[i]);
}

__global__ __launch_bounds__(256) void split_w_kernel(
    const float* __restrict__ Wq, const float* __restrict__ Wk,
    const float* __restrict__ Wv) {
  const int y = blockIdx.y;
  const float* W = (y == 0) ? Wq : (y == 1 ? Wk : Wv);
  size_t i = ((size_t)blockIdx.x * 256 + threadIdx.x) * 8;
  float4 f0 = *(const float4*)&W[i];
  float4 f1 = *(const float4*)&W[i + 4];
  float v[8] = {f0.x, f0.y, f0.z, f0.w, f1.x, f1.y, f1.z, f1.w};
  size_t o = (size_t)y * D_HEAD * D_IN + i;
  split8_store(v, &g_Wh[o], &g_Wl[o]);
}

// ---------------------------------------------------------------------------
// HMMA projection, double-buffered k-loop. BM=128, 256 threads, 2 CTAs/SM.
// ---------------------------------------------------------------------------
#define PSTR 80
#define PXH 0
#define PXL 10240
#define PWH 20480
#define PWL 30720
#define PSTAGE 40960
#define PROJ_SMEM (2 * PSTAGE)

__global__ __launch_bounds__(256, 2) void proj_mma_kernel() {
  extern __shared__ __align__(16) char psm[];
  const u32 pb = smem_u32(psm);

  const int y = blockIdx.y;
  const int bm = blockIdx.x;
  const int tid = threadIdx.x;
  const int w = tid >> 5;
  const int lane = tid & 31;
  const int g = lane >> 2;
  const int t = lane & 3;

  const char* xh = (const char*)g_Xh;
  const char* xl = (const char*)g_Xl;
  const char* wh = (const char*)(g_Wh + (size_t)y * D_HEAD * D_IN);
  const char* wl = (const char*)(g_Wl + (size_t)y * D_HEAD * D_IN);

  auto issue_chunk = [&](int kc32, int st) {
    const u32 base = pb + st * PSTAGE;
    const int k0 = kc32 * 32;
#pragma unroll
    for (int p = 0; p < 2; p++) {
      int idx = tid + 256 * p;           // 0..511
      int row = idx >> 2, sub = idx & 3;
      int so = row * PSTR + sub * 16;
      size_t xoff = ((size_t)(bm * 128 + row) * D_IN + k0) * 2 + sub * 16;
      size_t woff = ((size_t)row * D_IN + k0) * 2 + sub * 16;
      cp16(base + PXH + so, xh + xoff);
      cp16(base + PXL + so, xl + xoff);
      cp16(base + PWH + so, wh + woff);
      cp16(base + PWL + so, wl + woff);
    }
  };

  float o[16][4];
#pragma unroll
  for (int i = 0; i < 16; i++)
#pragma unroll
    for (int j = 0; j < 4; j++) o[i][j] = 0.0f;

  issue_chunk(0, 0);
  CP_COMMIT();

#pragma unroll 1
  for (int kc32 = 0; kc32 < 32; kc32++) {
    if (kc32 < 31) {
      issue_chunk(kc32 + 1, (kc32 + 1) & 1);
      CP_COMMIT();
      CP_WAIT1();
    } else {
      CP_WAIT0();
    }
    __syncthreads();

    const char* sm = psm + (kc32 & 1) * PSTAGE;
    const int oX = (16 * w + g) * PSTR + t * 4;
#pragma unroll
    for (int kc = 0; kc < 2; kc++) {
      const int qo = oX + kc * 32;
      u32 ah0 = *(const u32*)(sm + PXH + qo);
      u32 ah1 = *(const u32*)(sm + PXH + qo + 8 * PSTR);
      u32 ah2 = *(const u32*)(sm + PXH + qo + 16);
      u32 ah3 = *(const u32*)(sm + PXH + qo + 8 * PSTR + 16);
      u32 al0 = *(const u32*)(sm + PXL + qo);
      u32 al1 = *(const u32*)(sm + PXL + qo + 8 * PSTR);
      u32 al2 = *(const u32*)(sm + PXL + qo + 16);
      u32 al3 = *(const u32*)(sm + PXL + qo + 8 * PSTR + 16);
#pragma unroll
      for (int nf = 0; nf < 16; nf++) {
        const int bo = (8 * nf + g) * PSTR + t * 4 + kc * 32;
        u32 bh0 = *(const u32*)(sm + PWH + bo);
        u32 bh1 = *(const u32*)(sm + PWH + bo + 16);
        mma16816(o[nf], ah0, ah1, ah2, ah3, bh0, bh1);
        mma16816(o[nf], al0, al1, al2, al3, bh0, bh1);
        u32 bl0 = *(const u32*)(sm + PWL + bo);
        u32 bl1 = *(const u32*)(sm + PWL + bo + 16);
        mma16816(o[nf], ah0, ah1, ah2, ah3, bl0, bl1);
      }
    }
    __syncthreads();
  }

  const float scale = 11.313708498984760f;  // sqrt(128)
#pragma unroll
  for (int nf = 0; nf < 16; nf++) {
    int c0 = 8 * nf + 2 * t;
    int R0 = bm * 128 + 16 * w + g;
#pragma unroll
    for (int q = 0; q < 4; q++) {
      int R = R0 + (q >> 1) * 8;
      int c = c0 + (q & 1);
      float v = o[nf][q];
      __nv_bfloat16 h, l;
      if (y == 0) {
        split_bf16(v * scale, h, l);
        g_Qh[(size_t)R * D_HEAD + c] = h;
        g_Ql[(size_t)R * D_HEAD + c] = l;
      } else if (y == 1) {
        split_bf16(v, h, l);
        g_Kh[(size_t)R * D_HEAD + c] = h;
        g_Kl[(size_t)R * D_HEAD + c] = l;
      } else {
        split_bf16(v, h, l);
        size_t idx = (size_t)(R >> 7) * 16384 + (size_t)c * 128 + (R & 127);
        g_Vth[idx] = h;
        g_Vtl[idx] = l;
      }
    }
  }
}

// ---------------------------------------------------------------------------
// Pipelined HMMA flash kernel, 512 threads (16 warps = 4/SMSP).
// BM=64, BN=64/tile, 128 tiles. Warp w: rg=w&3 -> rows 16rg..+15,
// kh=w>>2 -> 16-key quarter. Per-kh split-K (m,l,O); 3-step smem merge epilogue.
// ---------------------------------------------------------------------------
#define RSTR 272
#define VSTR 144
#define SQH 0
#define SQL 17408
#define SBUF 34816
#define BKH 0
#define BKL 17408
#define BVH 34816
#define BVL 53248
#define BUFSZ 71680
#define SRED (SBUF + 2 * BUFSZ)        // 178176
#define ATT_SMEM (SRED + 1024)
// epilogue regions (alias tile buffers; only used after the loop)
#define OB0 SBUF
#define OB1 (SBUF + 32768)

__global__ __launch_bounds__(512, 1) void attn_kernel(float* __restrict__ Out) {
  extern __shared__ __align__(16) char smem[];
  const u32 sb = smem_u32(smem);

  const int tid = threadIdx.x;
  const int w = tid >> 5;
  const int lane = tid & 31;
  const int g = lane >> 2;
  const int t = lane & 3;
  const int rg = w & 3;
  const int kh = w >> 2;           // 0..3 key quarter
  const int qb = blockIdx.x;
  const int r0 = 16 * rg + g;
  const int r1 = r0 + 8;

  auto issue_K = [&](int tile, int b) {
    const u32 base = sb + SBUF + b * BUFSZ;
    const char* gkh = (const char*)g_Kh + (size_t)tile * 16384;
    const char* gkl = (const char*)g_Kl + (size_t)tile * 16384;
#pragma unroll
    for (int p = 0; p < 2; p++) {
      int idx = tid + 512 * p;           // 0..1023
      int kr = idx >> 4, ks = idx & 15;
      int so = kr * RSTR + ks * 16;
      cp16(base + BKH + so, gkh + idx * 16);
      cp16(base + BKL + so, gkl + idx * 16);
    }
  };
  auto issue_V = [&](int tile, int b) {
    const u32 base = sb + SBUF + b * BUFSZ;
    const size_t vbase = (size_t)(tile >> 1) * 32768 + (size_t)(tile & 1) * 128;
    const char* gvh = (const char*)g_Vth + vbase;
    const char* gvl = (const char*)g_Vtl + vbase;
#pragma unroll
    for (int p = 0; p < 2; p++) {
      int idx = tid + 512 * p;           // 0..1023
      int vd = idx >> 3, vs = idx & 7;
      int so = vd * VSTR + vs * 16;
      size_t voff = (size_t)vd * 256 + vs * 16;
      cp16(base + BVH + so, gvh + voff);
      cp16(base + BVL + so, gvl + voff);
    }
  };

  const int oQ = SQH + r0 * RSTR + t * 4;

  // S-phase MMAs: s += Q(rows) * K(buf b)^T for this warp's 16 keys
  auto mma_S = [&](float s[2][4], int b) {
    const int oK = SBUF + b * BUFSZ + BKH + (16 * kh + g) * RSTR + t * 4;
#pragma unroll
    for (int kc = 0; kc < 8; kc++) {
      const int qo = oQ + kc * 32;
      u32 ah0 = *(const u32*)(smem + qo);
      u32 ah1 = *(const u32*)(smem + qo + 8 * RSTR);
      u32 ah2 = *(const u32*)(smem + qo + 16);
      u32 ah3 = *(const u32*)(smem + qo + 8 * RSTR + 16);
      u32 al0 = *(const u32*)(smem + qo + 17408);
      u32 al1 = *(const u32*)(smem + qo + 17408 + 8 * RSTR);
      u32 al2 = *(const u32*)(smem + qo + 17408 + 16);
      u32 al3 = *(const u32*)(smem + qo + 17408 + 8 * RSTR + 16);
#pragma unroll
      for (int nf = 0; nf < 2; nf++) {
        const int bo = oK + nf * 8 * RSTR + kc * 32;
        u32 bh0 = *(const u32*)(smem + bo);
        u32 bh1 = *(const u32*)(smem + bo + 16);
        mma16816(s[nf], ah0, ah1, ah2, ah3, bh0, bh1);
        mma16816(s[nf], al0, al1, al2, al3, bh0, bh1);
        u32 bl0 = *(const u32*)(smem + bo + 17408);
        u32 bl1 = *(const u32*)(smem + bo + 17408 + 16);
        mma16816(s[nf], ah0, ah1, ah2, ah3, bl0, bl1);
      }
    }
  };

  // ---- prologue ----
  {
    const char* gqh = (const char*)g_Qh + (size_t)qb * 16384;
    const char* gql = (const char*)g_Ql + (size_t)qb * 16384;
#pragma unroll
    for (int p = 0; p < 2; p++) {
      int idx = tid + 512 * p;
      int row = idx >> 4, sub = idx & 15;
      int so = row * RSTR + sub * 16;
      cp16(sb + SQH + so, gqh + idx * 16);
      cp16(sb + SQL + so, gql + idx * 16);
    }
    issue_K(0, 0);
    issue_V(0, 0);
    CP_COMMIT();
    issue_K(1, 1);
    CP_COMMIT();
    issue_V(1, 1);
    CP_COMMIT();
  }

  float o[16][4];
#pragma unroll
  for (int i = 0; i < 16; i++)
#pragma unroll
    for (int j = 0; j < 4; j++) o[i][j] = 0.0f;
  float m0 = -1e30f, m1 = -1e30f, l0 = 0.0f, l1 = 0.0f;

  float s_cur[2][4], s_next[2][4];

  CP_WAIT2();
  __syncthreads();
#pragma unroll
  for (int i = 0; i < 2; i++)
#pragma unroll
    for (int j = 0; j < 4; j++) s_cur[i][j] = 0.0f;
  mma_S(s_cur, 0);

#pragma unroll 1
  for (int tile = 0; tile < 128; ++tile) {
    if (tile < 127) CP_WAIT1(); else CP_WAIT0();
    __syncthreads();

    if (tile < 126) {
      issue_K(tile + 2, tile & 1);
      CP_COMMIT();
    }

    // ---- phase A: S(t+1), independent of softmax/PV below ----
    if (tile < 127) {
#pragma unroll
      for (int i = 0; i < 2; i++)
#pragma unroll
        for (int j = 0; j < 4; j++) s_next[i][j] = 0.0f;
      mma_S(s_next, (tile + 1) & 1);
    }

    // ---- phase B: warp-local softmax (per-kh split-K state) ----
    float mt0 = fmaxf(fmaxf(s_cur[0][0], s_cur[0][1]), fmaxf(s_cur[1][0], s_cur[1][1]));
    float mt1 = fmaxf(fmaxf(s_cur[0][2], s_cur[0][3]), fmaxf(s_cur[1][2], s_cur[1][3]));
#pragma unroll
    for (int off = 1; off <= 2; off <<= 1) {
      mt0 = fmaxf(mt0, __shfl_xor_sync(0xffffffffu, mt0, off));
      mt1 = fmaxf(mt1, __shfl_xor_sync(0xffffffffu, mt1, off));
    }
    const float mn0 = fmaxf(m0, mt0), mn1 = fmaxf(m1, mt1);
    const float a0f = __expf(m0 - mn0), a1f = __expf(m1 - mn1);
    m0 = mn0; m1 = mn1;

    float sum0 = 0.0f, sum1 = 0.0f;
#pragma unroll
    for (int nf = 0; nf < 2; nf++) {
      s_cur[nf][0] = __expf(s_cur[nf][0] - mn0); sum0 += s_cur[nf][0];
      s_cur[nf][1] = __expf(s_cur[nf][1] - mn0); sum0 += s_cur[nf][1];
      s_cur[nf][2] = __expf(s_cur[nf][2] - mn1); sum1 += s_cur[nf][2];
      s_cur[nf][3] = __expf(s_cur[nf][3] - mn1); sum1 += s_cur[nf][3];
    }
#pragma unroll
    for (int off = 1; off <= 2; off <<= 1) {
      sum0 += __shfl_xor_sync(0xffffffffu, sum0, off);
      sum1 += __shfl_xor_sync(0xffffffffu, sum1, off);
    }
    l0 = l0 * a0f + sum0;
    l1 = l1 * a1f + sum1;

#pragma unroll
    for (int i = 0; i < 16; i++) {
      o[i][0] *= a0f; o[i][1] *= a0f;
      o[i][2] *= a1f; o[i][3] *= a1f;
    }

    // ---- pack P hi/lo into PV A-frags (registers only) ----
    u32 ph[4], pl[4];
    {
      float e[8] = { s_cur[0][0], s_cur[0][1], s_cur[0][2], s_cur[0][3],
                     s_cur[1][0], s_cur[1][1], s_cur[1][2], s_cur[1][3] };
      const int map[4][2] = {{0,1},{2,3},{4,5},{6,7}};
#pragma unroll
      for (int q = 0; q < 4; q++) {
        float x0 = e[map[q][0]], x1 = e[map[q][1]];
        u32 hp = cvt2(x1, x0);
        float h0 = __uint_as_float(hp << 16);
        float h1 = __uint_as_float(hp & 0xffff0000u);
        ph[q] = hp;
        pl[q] = cvt2(x1 - h1, x0 - h0);
      }
    }

    // ---- O += P V over this warp's 16 keys ----
    const int oV = SBUF + (tile & 1) * BUFSZ + BVH + g * VSTR + t * 4 + kh * 32;
#pragma unroll
    for (int nf2 = 0; nf2 < 16; nf2++) {
      const int vb = oV + nf2 * 8 * VSTR;
      u32 bh0 = *(const u32*)(smem + vb);
      u32 bh1 = *(const u32*)(smem + vb + 16);
      mma16816(o[nf2], ph[0], ph[1], ph[2], ph[3], bh0, bh1);
      mma16816(o[nf2], pl[0], pl[1], pl[2], pl[3], bh0, bh1);
      u32 bl0 = *(const u32*)(smem + vb + 18432);
      u32 bl1 = *(const u32*)(smem + vb + 18432 + 16);
      mma16816(o[nf2], ph[0], ph[1], ph[2], ph[3], bl0, bl1);
    }

    __syncthreads();   // V buffer fully consumed
    if (tile < 126) {
      issue_V(tile + 2, tile & 1);
      CP_COMMIT();
    }

#pragma unroll
    for (int i = 0; i < 2; i++)
#pragma unroll
      for (int j = 0; j < 4; j++) s_cur[i][j] = s_next[i][j];
  }

  // ---- epilogue: 3-step merge of the 4 kh split-K states ----
  float* Ob0 = (float*)(smem + OB0);
  float* Ob1 = (float*)(smem + OB1);
  float* marr = (float*)(smem + SRED);        // [2][64]
  float* larr = marr + 128;                   // [2][64]

  auto write_state = [&](float* Ob, int mi) {
#pragma unroll
    for (int nf2 = 0; nf2 < 16; nf2++) {
      int c0 = 8 * nf2 + 2 * t;
      Ob[r0 * 128 + c0]     = o[nf2][0];
      Ob[r0 * 128 + c0 + 1] = o[nf2][1];
      Ob[r1 * 128 + c0]     = o[nf2][2];
      Ob[r1 * 128 + c0 + 1] = o[nf2][3];
    }
    if (t == 0) {
      marr[mi * 64 + r0] = m0; larr[mi * 64 + r0] = l0;
      marr[mi * 64 + r1] = m1; larr[mi * 64 + r1] = l1;
    }
  };
  auto merge_state = [&](const float* Ob, int mi) {
    float pm0 = marr[mi * 64 + r0], pL0 = larr[mi * 64 + r0];
    float pm1 = marr[mi * 64 + r1], pL1 = larr[mi * 64 + r1];
    float M0 = fmaxf(m0, pm0), M1 = fmaxf(m1, pm1);
    float as0 = __expf(m0 - M0), ao0 = __expf(pm0 - M0);
    float as1 = __expf(m1 - M1), ao1 = __expf(pm1 - M1);
    l0 = as0 * l0 + ao0 * pL0;
    l1 = as1 * l1 + ao1 * pL1;
    m0 = M0; m1 = M1;
#pragma unroll
    for (int nf2 = 0; nf2 < 16; nf2++) {
      int c0 = 8 * nf2 + 2 * t;
      o[nf2][0] = as0 * o[nf2][0] + ao0 * Ob[r0 * 128 + c0];
      o[nf2][1] = as0 * o[nf2][1] + ao0 * Ob[r0 * 128 + c0 + 1];
      o[nf2][2] = as1 * o[nf2][2] + ao1 * Ob[r1 * 128 + c0];
      o[nf2][3] = as1 * o[nf2][3] + ao1 * Ob[r1 * 128 + c0 + 1];
    }
  };

  if (kh == 2) write_state(Ob0, 0);
  if (kh == 3) write_state(Ob1, 1);
  __syncthreads();
  if (kh == 0) merge_state(Ob0, 0);
  if (kh == 1) merge_state(Ob1, 1);
  __syncthreads();
  if (kh == 1) write_state(Ob0, 0);
  __syncthreads();
  if (kh == 0) {
    merge_state(Ob0, 0);
    const float inv0 = 1.0f / l0, inv1 = 1.0f / l1;
#pragma unroll
    for (int nf2 = 0; nf2 < 16; nf2++) {
      int c0 = 8 * nf2 + 2 * t;
      *(float2*)&Out[(size_t)(qb * 64 + r0) * D_HEAD + c0] =
          make_float2(o[nf2][0] * inv0, o[nf2][1] * inv0);
      *(float2*)&Out[(size_t)(qb * 64 + r1) * D_HEAD + c0] =
          make_float2(o[nf2][2] * inv1, o[nf2][3] * inv1);
    }
  }
}

// ---------------------------------------------------------------------------
extern "C" void kernel_launch(void* const* d_in, const int* in_sizes, int n_in,
                              void* d_out, int out_size) {
  const float* x  = (const float*)d_in[0];
  const float* Wq = (const float*)d_in[1];
  const float* Wk = (const float*)d_in[2];
  const float* Wv = (const float*)d_in[3];
  float* out = (float*)d_out;

  cudaFuncSetAttribute(attn_kernel,
                       cudaFuncAttributeMaxDynamicSharedMemorySize, ATT_SMEM);
  cudaFuncSetAttribute(proj_mma_kernel,
                       cudaFuncAttributeMaxDynamicSharedMemorySize, PROJ_SMEM);

  split_x_kernel<<<(N_TOK * D_IN) / 2048, 256>>>(x);
  split_w_kernel<<<dim3((D_HEAD * D_IN) / 2048, 3), 256>>>(Wq, Wk, Wv);
  proj_mma_kernel<<<dim3(N_TOK / 128, 3), 256, PROJ_SMEM>>>();
  attn_kernel<<<N_TOK / 64, 512, ATT_SMEM>>>(out);
}

// round 8
// speedup vs baseline: 1.0686x; 1.0686x over previous
#include <cuda_runtime.h>
#include <cuda_bf16.h>
#include <math.h>
#include <stdint.h>

#define N_TOK 8192
#define D_IN  1024
#define D_HEAD 128

typedef uint32_t u32;

// ---------------------------------------------------------------------------
// Device-global scratch.
// ---------------------------------------------------------------------------
__device__ __align__(16) __nv_bfloat16 g_Xh[(size_t)N_TOK * D_IN];
__device__ __align__(16) __nv_bfloat16 g_Xl[(size_t)N_TOK * D_IN];
__device__ __align__(16) __nv_bfloat16 g_Wh[3 * D_HEAD * D_IN];
__device__ __align__(16) __nv_bfloat16 g_Wl[3 * D_HEAD * D_IN];
__device__ __align__(16) __nv_bfloat16 g_Qh[N_TOK * D_HEAD];
__device__ __align__(16) __nv_bfloat16 g_Ql[N_TOK * D_HEAD];
__device__ __align__(16) __nv_bfloat16 g_Kh[N_TOK * D_HEAD];
__device__ __align__(16) __nv_bfloat16 g_Kl[N_TOK * D_HEAD];
__device__ __align__(16) __nv_bfloat16 g_Vth[N_TOK * D_HEAD];
__device__ __align__(16) __nv_bfloat16 g_Vtl[N_TOK * D_HEAD];

__device__ __forceinline__ void split_bf16(float v, __nv_bfloat16& h, __nv_bfloat16& l) {
  h = __float2bfloat16(v);
  l = __float2bfloat16(v - __bfloat162float(h));
}

__device__ __forceinline__ u32 smem_u32(const void* p) {
  u32 a;
  asm("{ .reg .u64 t; cvta.to.shared.u64 t, %1; cvt.u32.u64 %0, t; }" : "=r"(a) : "l"(p));
  return a;
}
__device__ __forceinline__ void cp16(u32 dst, const void* src) {
  asm volatile("cp.async.cg.shared.global [%0], [%1], 16;" :: "r"(dst), "l"(src));
}
#define CP_COMMIT() asm volatile("cp.async.commit_group;" ::: "memory")
#define CP_WAIT0()  asm volatile("cp.async.wait_group 0;" ::: "memory")
#define CP_WAIT1()  asm volatile("cp.async.wait_group 1;" ::: "memory")
#define CP_WAIT2()  asm volatile("cp.async.wait_group 2;" ::: "memory")

// m16n8k16 row.col bf16 -> f32 (HMMA; portable PTX)
__device__ __forceinline__ void mma16816(float* d, const u32* a, u32 b0, u32 b1) {
  asm volatile(
      "mma.sync.aligned.m16n8k16.row.col.f32.bf16.bf16.f32 "
      "{%0,%1,%2,%3}, {%4,%5,%6,%7}, {%8,%9}, {%0,%1,%2,%3};"
      : "+f"(d[0]), "+f"(d[1]), "+f"(d[2]), "+f"(d[3])
      : "r"(a[0]), "r"(a[1]), "r"(a[2]), "r"(a[3]), "r"(b0), "r"(b1));
}
// ldmatrix x4: loads 4 8x8 b16 matrices. Lane L supplies the address of
// 16B row (L&15 within the 16-row span; (L>>4)*8 column offset).
__device__ __forceinline__ void ldsm4(u32* r, u32 addr) {
  asm volatile("ldmatrix.sync.aligned.m8n8.x4.shared.b16 {%0,%1,%2,%3}, [%4];"
               : "=r"(r[0]), "=r"(r[1]), "=r"(r[2]), "=r"(r[3]) : "r"(addr));
}
__device__ __forceinline__ u32 cvt2(float hi, float lo) {
  u32 d;
  asm("cvt.rn.bf16x2.f32 %0, %1, %2;" : "=r"(d) : "f"(hi), "f"(lo));
  return d;
}

// ---------------------------------------------------------------------------
// Split kernels: fp32 -> bf16 hi/lo.
// ---------------------------------------------------------------------------
__device__ __forceinline__ void split8_store(const float* v, __nv_bfloat16* dh,
                                             __nv_bfloat16* dl) {
  u32 hw[4], lw[4];
#pragma unroll
  for (int j = 0; j < 4; j++) {
    __nv_bfloat16 h0, l0, h1, l1;
    split_bf16(v[2 * j], h0, l0);
    split_bf16(v[2 * j + 1], h1, l1);
    hw[j] = ((u32)__bfloat16_as_ushort(h1) << 16) | __bfloat16_as_ushort(h0);
    lw[j] = ((u32)__bfloat16_as_ushort(l1) << 16) | __bfloat16_as_ushort(l0);
  }
  *(uint4*)dh = make_uint4(hw[0], hw[1], hw[2], hw[3]);
  *(uint4*)dl = make_uint4(lw[0], lw[1], lw[2], lw[3]);
}

__global__ __launch_bounds__(256) void split_x_kernel(const float* __restrict__ X) {
  size_t i = ((size_t)blockIdx.x * 256 + threadIdx.x) * 8;
  float4 f0 = *(const float4*)&X[i];
  float4 f1 = *(const float4*)&X[i + 4];
  float v[8] = {f0.x, f0.y, f0.z, f0.w, f1.x, f1.y, f1.z, f1.w};
  split8_store(v, &g_Xh[i], &g_Xl[i]);
}

__global__ __launch_bounds__(256) void split_w_kernel(
    const float* __restrict__ Wq, const float* __restrict__ Wk,
    const float* __restrict__ Wv) {
  const int y = blockIdx.y;
  const float* W = (y == 0) ? Wq : (y == 1 ? Wk : Wv);
  size_t i = ((size_t)blockIdx.x * 256 + threadIdx.x) * 8;
  float4 f0 = *(const float4*)&W[i];
  float4 f1 = *(const float4*)&W[i + 4];
  float v[8] = {f0.x, f0.y, f0.z, f0.w, f1.x, f1.y, f1.z, f1.w};
  size_t o = (size_t)y * D_HEAD * D_IN + i;
  split8_store(v, &g_Wh[o], &g_Wl[o]);
}

// ---------------------------------------------------------------------------
// HMMA projection, double-buffered k-loop, LDSM frag loads.
// BM=128, 256 threads, 2 CTAs/SM.
// ---------------------------------------------------------------------------
#define PSTR 80
#define PXH 0
#define PXL 10240
#define PWH 20480
#define PWL 30720
#define PSTAGE 40960
#define PROJ_SMEM (2 * PSTAGE)

__global__ __launch_bounds__(256, 2) void proj_mma_kernel() {
  extern __shared__ __align__(16) char psm[];
  const u32 pb = smem_u32(psm);

  const int y = blockIdx.y;
  const int bm = blockIdx.x;
  const int tid = threadIdx.x;
  const int w = tid >> 5;
  const int lane = tid & 31;
  const int t = lane & 3;
  const int lrow = lane & 15;
  const int lcol8 = (lane >> 4) * 8;

  const char* xh = (const char*)g_Xh;
  const char* xl = (const char*)g_Xl;
  const char* wh = (const char*)(g_Wh + (size_t)y * D_HEAD * D_IN);
  const char* wl = (const char*)(g_Wl + (size_t)y * D_HEAD * D_IN);

  auto issue_chunk = [&](int kc32, int st) {
    const u32 base = pb + st * PSTAGE;
    const int k0 = kc32 * 32;
#pragma unroll
    for (int p = 0; p < 2; p++) {
      int idx = tid + 256 * p;           // 0..511
      int row = idx >> 2, sub = idx & 3;
      int so = row * PSTR + sub * 16;
      size_t xoff = ((size_t)(bm * 128 + row) * D_IN + k0) * 2 + sub * 16;
      size_t woff = ((size_t)row * D_IN + k0) * 2 + sub * 16;
      cp16(base + PXH + so, xh + xoff);
      cp16(base + PXL + so, xl + xoff);
      cp16(base + PWH + so, wh + woff);
      cp16(base + PWL + so, wl + woff);
    }
  };

  float o[16][4];
#pragma unroll
  for (int i = 0; i < 16; i++)
#pragma unroll
    for (int j = 0; j < 4; j++) o[i][j] = 0.0f;

  issue_chunk(0, 0);
  CP_COMMIT();

  // lane-based LDSM addresses (stage-relative)
  const u32 aX0 = (16 * w + lrow) * PSTR + lcol8 * 2;
  const u32 aW0 = lrow * PSTR + lcol8 * 2;

#pragma unroll 1
  for (int kc32 = 0; kc32 < 32; kc32++) {
    if (kc32 < 31) {
      issue_chunk(kc32 + 1, (kc32 + 1) & 1);
      CP_COMMIT();
      CP_WAIT1();
    } else {
      CP_WAIT0();
    }
    __syncthreads();

    const u32 sbase = pb + (kc32 & 1) * PSTAGE;
#pragma unroll
    for (int kc = 0; kc < 2; kc++) {
      u32 ah[4], al[4];
      ldsm4(ah, sbase + PXH + aX0 + kc * 32);
      ldsm4(al, sbase + PXL + aX0 + kc * 32);
#pragma unroll
      for (int nw = 0; nw < 8; nw++) {
        u32 bh[4], bl[4];
        ldsm4(bh, sbase + PWH + aW0 + nw * 16 * PSTR + kc * 32);
        ldsm4(bl, sbase + PWL + aW0 + nw * 16 * PSTR + kc * 32);
        // nf=2nw: b0=m0,b1=m2 ; nf=2nw+1: b0=m1,b1=m3
        mma16816(o[2 * nw],     ah, bh[0], bh[2]);
        mma16816(o[2 * nw],     al, bh[0], bh[2]);
        mma16816(o[2 * nw],     ah, bl[0], bl[2]);
        mma16816(o[2 * nw + 1], ah, bh[1], bh[3]);
        mma16816(o[2 * nw + 1], al, bh[1], bh[3]);
        mma16816(o[2 * nw + 1], ah, bl[1], bl[3]);
      }
    }
    __syncthreads();
  }

  const float scale = 11.313708498984760f;  // sqrt(128)
  const int g = lane >> 2;
#pragma unroll
  for (int nf = 0; nf < 16; nf++) {
    int c0 = 8 * nf + 2 * t;
    int R0 = bm * 128 + 16 * w + g;
#pragma unroll
    for (int q = 0; q < 4; q++) {
      int R = R0 + (q >> 1) * 8;
      int c = c0 + (q & 1);
      float v = o[nf][q];
      __nv_bfloat16 h, l;
      if (y == 0) {
        split_bf16(v * scale, h, l);
        g_Qh[(size_t)R * D_HEAD + c] = h;
        g_Ql[(size_t)R * D_HEAD + c] = l;
      } else if (y == 1) {
        split_bf16(v, h, l);
        g_Kh[(size_t)R * D_HEAD + c] = h;
        g_Kl[(size_t)R * D_HEAD + c] = l;
      } else {
        split_bf16(v, h, l);
        size_t idx = (size_t)(R >> 7) * 16384 + (size_t)c * 128 + (R & 127);
        g_Vth[idx] = h;
        g_Vtl[idx] = l;
      }
    }
  }
}

// ---------------------------------------------------------------------------
// Pipelined HMMA flash kernel (R6 geometry) with LDSM frag loads.
// BM=64, BN=64/tile, 128 tiles, double-buffered, S(t+1) prefetch.
// 8 warps: rg=w&3 -> rows 16rg..+15, kh=w>>2 -> 32-key half. Split-K per kh.
// ---------------------------------------------------------------------------
#define RSTR 272
#define VSTR 144
#define SQH 0
#define SQL 17408
#define SBUF 34816
#define BKH 0
#define BKL 17408
#define BVH 34816
#define BVL 53248
#define BUFSZ 71680
#define SRED (SBUF + 2 * BUFSZ)        // 178176
#define ATT_SMEM (SRED + 1024)

__global__ __launch_bounds__(256, 1) void attn_kernel(float* __restrict__ Out) {
  extern __shared__ __align__(16) char smem[];
  const u32 sb = smem_u32(smem);

  const int tid = threadIdx.x;
  const int w = tid >> 5;
  const int lane = tid & 31;
  const int g = lane >> 2;
  const int t = lane & 3;
  const int rg = w & 3;
  const int kh = w >> 2;
  const int qb = blockIdx.x;
  const int r0 = 16 * rg + g;
  const int r1 = r0 + 8;
  const int lrow = lane & 15;
  const int lcol8 = (lane >> 4) * 8;

  auto issue_K = [&](int tile, int b) {
    const u32 base = sb + SBUF + b * BUFSZ;
    const char* gkh = (const char*)g_Kh + (size_t)tile * 16384;
    const char* gkl = (const char*)g_Kl + (size_t)tile * 16384;
#pragma unroll
    for (int p = 0; p < 4; p++) {
      int idx = tid + 256 * p;           // 0..1023
      int kr = idx >> 4, ks = idx & 15;
      int so = kr * RSTR + ks * 16;
      cp16(base + BKH + so, gkh + idx * 16);
      cp16(base + BKL + so, gkl + idx * 16);
    }
  };
  auto issue_V = [&](int tile, int b) {
    const u32 base = sb + SBUF + b * BUFSZ;
    const size_t vbase = (size_t)(tile >> 1) * 32768 + (size_t)(tile & 1) * 128;
    const char* gvh = (const char*)g_Vth + vbase;
    const char* gvl = (const char*)g_Vtl + vbase;
#pragma unroll
    for (int p = 0; p < 4; p++) {
      int idx = tid + 256 * p;           // 0..1023
      int vd = idx >> 3, vs = idx & 7;
      int so = vd * VSTR + vs * 16;
      size_t voff = (size_t)vd * 256 + vs * 16;
      cp16(base + BVH + so, gvh + voff);
      cp16(base + BVL + so, gvl + voff);
    }
  };

  // lane-based LDSM base addresses
  const u32 aQ = sb + SQH + (16 * rg + lrow) * RSTR + lcol8 * 2;   // + 17408 for lo
  const u32 aK0 = SBUF + BKH + (32 * kh + lrow) * RSTR + lcol8 * 2; // + b*BUFSZ
  const u32 aV0 = SBUF + BVH + lrow * VSTR + (32 * kh + lcol8) * 2; // + b*BUFSZ

  // S-phase MMAs via LDSM: s += Q(rows) * K(buf b)^T for this warp's 32 keys
  auto mma_S = [&](float s[4][4], int b) {
    const u32 aKb = sb + aK0 + b * BUFSZ;
#pragma unroll
    for (int kc = 0; kc < 8; kc++) {
      u32 qh[4], ql[4];
      ldsm4(qh, aQ + kc * 32);
      ldsm4(ql, aQ + 17408 + kc * 32);
      u32 k0h[4], k1h[4], k0l[4], k1l[4];
      ldsm4(k0h, aKb + kc * 32);
      ldsm4(k1h, aKb + 16 * RSTR + kc * 32);
      ldsm4(k0l, aKb + 17408 + kc * 32);
      ldsm4(k1l, aKb + 17408 + 16 * RSTR + kc * 32);
      mma16816(s[0], qh, k0h[0], k0h[2]);
      mma16816(s[0], ql, k0h[0], k0h[2]);
      mma16816(s[0], qh, k0l[0], k0l[2]);
      mma16816(s[1], qh, k0h[1], k0h[3]);
      mma16816(s[1], ql, k0h[1], k0h[3]);
      mma16816(s[1], qh, k0l[1], k0l[3]);
      mma16816(s[2], qh, k1h[0], k1h[2]);
      mma16816(s[2], ql, k1h[0], k1h[2]);
      mma16816(s[2], qh, k1l[0], k1l[2]);
      mma16816(s[3], qh, k1h[1], k1h[3]);
      mma16816(s[3], ql, k1h[1], k1h[3]);
      mma16816(s[3], qh, k1l[1], k1l[3]);
    }
  };

  // ---- prologue ----
  {
    const char* gqh = (const char*)g_Qh + (size_t)qb * 16384;
    const char* gql = (const char*)g_Ql + (size_t)qb * 16384;
#pragma unroll
    for (int p = 0; p < 4; p++) {
      int idx = tid + 256 * p;
      int row = idx >> 4, sub = idx & 15;
      int so = row * RSTR + sub * 16;
      cp16(sb + SQH + so, gqh + idx * 16);
      cp16(sb + SQL + so, gql + idx * 16);
    }
    issue_K(0, 0);
    issue_V(0, 0);
    CP_COMMIT();
    issue_K(1, 1);
    CP_COMMIT();
    issue_V(1, 1);
    CP_COMMIT();
  }

  float o[16][4];
#pragma unroll
  for (int i = 0; i < 16; i++)
#pragma unroll
    for (int j = 0; j < 4; j++) o[i][j] = 0.0f;
  float m0 = -1e30f, m1 = -1e30f, l0 = 0.0f, l1 = 0.0f;

  float s_cur[4][4], s_next[4][4];

  CP_WAIT2();
  __syncthreads();
#pragma unroll
  for (int i = 0; i < 4; i++)
#pragma unroll
    for (int j = 0; j < 4; j++) s_cur[i][j] = 0.0f;
  mma_S(s_cur, 0);

#pragma unroll 1
  for (int tile = 0; tile < 128; ++tile) {
    if (tile < 127) CP_WAIT1(); else CP_WAIT0();
    __syncthreads();

    if (tile < 126) {
      issue_K(tile + 2, tile & 1);
      CP_COMMIT();
    }

    // ---- phase A: S(t+1), independent of softmax/PV below ----
    if (tile < 127) {
#pragma unroll
      for (int i = 0; i < 4; i++)
#pragma unroll
        for (int j = 0; j < 4; j++) s_next[i][j] = 0.0f;
      mma_S(s_next, (tile + 1) & 1);
    }

    // ---- phase B: warp-local softmax (per-kh split-K state) ----
    float mt0 = -1e30f, mt1 = -1e30f;
#pragma unroll
    for (int nf = 0; nf < 4; nf++) {
      mt0 = fmaxf(mt0, fmaxf(s_cur[nf][0], s_cur[nf][1]));
      mt1 = fmaxf(mt1, fmaxf(s_cur[nf][2], s_cur[nf][3]));
    }
#pragma unroll
    for (int off = 1; off <= 2; off <<= 1) {
      mt0 = fmaxf(mt0, __shfl_xor_sync(0xffffffffu, mt0, off));
      mt1 = fmaxf(mt1, __shfl_xor_sync(0xffffffffu, mt1, off));
    }
    const float mn0 = fmaxf(m0, mt0), mn1 = fmaxf(m1, mt1);
    const float a0f = __expf(m0 - mn0), a1f = __expf(m1 - mn1);
    m0 = mn0; m1 = mn1;

    float sum0 = 0.0f, sum1 = 0.0f;
#pragma unroll
    for (int nf = 0; nf < 4; nf++) {
      s_cur[nf][0] = __expf(s_cur[nf][0] - mn0); sum0 += s_cur[nf][0];
      s_cur[nf][1] = __expf(s_cur[nf][1] - mn0); sum0 += s_cur[nf][1];
      s_cur[nf][2] = __expf(s_cur[nf][2] - mn1); sum1 += s_cur[nf][2];
      s_cur[nf][3] = __expf(s_cur[nf][3] - mn1); sum1 += s_cur[nf][3];
    }
#pragma unroll
    for (int off = 1; off <= 2; off <<= 1) {
      sum0 += __shfl_xor_sync(0xffffffffu, sum0, off);
      sum1 += __shfl_xor_sync(0xffffffffu, sum1, off);
    }
    l0 = l0 * a0f + sum0;
    l1 = l1 * a1f + sum1;

#pragma unroll
    for (int i = 0; i < 16; i++) {
      o[i][0] *= a0f; o[i][1] *= a0f;
      o[i][2] *= a1f; o[i][3] *= a1f;
    }

    // ---- pack P hi/lo into PV A-frags (registers only) ----
    u32 ph[2][4], pl[2][4];
#pragma unroll
    for (int c = 0; c < 2; c++) {
      float e[8] = { s_cur[2*c][0],   s_cur[2*c][1],   s_cur[2*c][2],   s_cur[2*c][3],
                     s_cur[2*c+1][0], s_cur[2*c+1][1], s_cur[2*c+1][2], s_cur[2*c+1][3] };
      const int map[4][2] = {{0,1},{2,3},{4,5},{6,7}};
#pragma unroll
      for (int q = 0; q < 4; q++) {
        float x0 = e[map[q][0]], x1 = e[map[q][1]];
        u32 hp = cvt2(x1, x0);
        float h0 = __uint_as_float(hp << 16);
        float h1 = __uint_as_float(hp & 0xffff0000u);
        ph[c][q] = hp;
        pl[c][q] = cvt2(x1 - h1, x0 - h0);
      }
    }

    // ---- O += P V over this warp's 32 keys (LDSM V frags) ----
    const u32 aVb = sb + aV0 + (tile & 1) * BUFSZ;
#pragma unroll
    for (int c = 0; c < 2; c++) {
#pragma unroll
      for (int dq = 0; dq < 8; dq++) {
        u32 vh[4], vl[4];
        const u32 av = aVb + dq * 16 * VSTR + c * 32;
        ldsm4(vh, av);
        ldsm4(vl, av + 18432);
        mma16816(o[2 * dq],     ph[c], vh[0], vh[2]);
        mma16816(o[2 * dq],     pl[c], vh[0], vh[2]);
        mma16816(o[2 * dq],     ph[c], vl[0], vl[2]);
        mma16816(o[2 * dq + 1], ph[c], vh[1], vh[3]);
        mma16816(o[2 * dq + 1], pl[c], vh[1], vh[3]);
        mma16816(o[2 * dq + 1], ph[c], vl[1], vl[3]);
      }
    }

    __syncthreads();   // V buffer fully consumed
    if (tile < 126) {
      issue_V(tile + 2, tile & 1);
      CP_COMMIT();
    }

#pragma unroll
    for (int i = 0; i < 4; i++)
#pragma unroll
      for (int j = 0; j < 4; j++) s_cur[i][j] = s_next[i][j];
  }

  // ---- epilogue: merge kh=0 / kh=1 split-K states, normalize, store ----
  float* Ob = (float*)(smem + SBUF);    // 64 x 128 f32
  float* redm = (float*)(smem + SRED);
  float* redl = redm + 64;
  if (kh == 0) {
#pragma unroll
    for (int nf2 = 0; nf2 < 16; nf2++) {
      int c0 = 8 * nf2 + 2 * t;
      Ob[r0 * 128 + c0]     = o[nf2][0];
      Ob[r0 * 128 + c0 + 1] = o[nf2][1];
      Ob[r1 * 128 + c0]     = o[nf2][2];
      Ob[r1 * 128 + c0 + 1] = o[nf2][3];
    }
    if (t == 0) {
      redm[r0] = m0; redl[r0] = l0;
      redm[r1] = m1; redl[r1] = l1;
    }
  }
  __syncthreads();
  if (kh == 1) {
    float pm0 = redm[r0], pL0 = redl[r0];
    float pm1 = redm[r1], pL1 = redl[r1];
    float M0 = fmaxf(m0, pm0), M1 = fmaxf(m1, pm1);
    float w1_0 = __expf(m0 - M0), w0_0 = __expf(pm0 - M0);
    float w1_1 = __expf(m1 - M1), w0_1 = __expf(pm1 - M1);
    float inv0 = 1.0f / (w0_0 * pL0 + w1_0 * l0);
    float inv1 = 1.0f / (w0_1 * pL1 + w1_1 * l1);
#pragma unroll
    for (int nf2 = 0; nf2 < 16; nf2++) {
      int c0 = 8 * nf2 + 2 * t;
      float v00 = (w1_0 * o[nf2][0] + w0_0 * Ob[r0 * 128 + c0])     * inv0;
      float v01 = (w1_0 * o[nf2][1] + w0_0 * Ob[r0 * 128 + c0 + 1]) * inv0;
      float v10 = (w1_1 * o[nf2][2] + w0_1 * Ob[r1 * 128 + c0])     * inv1;
      float v11 = (w1_1 * o[nf2][3] + w0_1 * Ob[r1 * 128 + c0 + 1]) * inv1;
      *(float2*)&Out[(size_t)(qb * 64 + r0) * D_HEAD + c0] = make_float2(v00, v01);
      *(float2*)&Out[(size_t)(qb * 64 + r1) * D_HEAD + c0] = make_float2(v10, v11);
    }
  }
}

// ---------------------------------------------------------------------------
extern "C" void kernel_launch(void* const* d_in, const int* in_sizes, int n_in,
                              void* d_out, int out_size) {
  const float* x  = (const float*)d_in[0];
  const float* Wq = (const float*)d_in[1];
  const float* Wk = (const float*)d_in[2];
  const float* Wv = (const float*)d_in[3];
  float* out = (float*)d_out;

  cudaFuncSetAttribute(attn_kernel,
                       cudaFuncAttributeMaxDynamicSharedMemorySize, ATT_SMEM);
  cudaFuncSetAttribute(proj_mma_kernel,
                       cudaFuncAttributeMaxDynamicSharedMemorySize, PROJ_SMEM);

  split_x_kernel<<<(N_TOK * D_IN) / 2048, 256>>>(x);
  split_w_kernel<<<dim3((D_HEAD * D_IN) / 2048, 3), 256>>>(Wq, Wk, Wv);
  proj_mma_kernel<<<dim3(N_TOK / 128, 3), 256, PROJ_SMEM>>>();
  attn_kernel<<<N_TOK / 64, 256, ATT_SMEM>>>(out);
}